// round 13
// baseline (speedup 1.0000x reference)
#include <cuda_runtime.h>
#include <cstdint>

#define Bdim 4
#define Hdim 32
#define Tdim 2048
#define Kdim 64
#define Vdim 64
#define VH 32                      // v-columns per block (V split in 2)
#define CHUNK 32
#define NCHUNK (Tdim / CHUNK)
#define NTHREADS 256
#define CB_QKW (CHUNK * Kdim * 4)  // 8192 B per chunk for q/k/w
#define CB_V   (CHUNK * VH * 4)    // 4096 B per chunk for v-half

// ---- packed f32x2 helpers (sm_103a FFMA2 path) ----
__device__ __forceinline__ float2 fma2(float2 a, float2 b, float2 c) {
    float2 d;
    asm("fma.rn.f32x2 %0, %1, %2, %3;"
        : "=l"(reinterpret_cast<unsigned long long&>(d))
        : "l"(reinterpret_cast<unsigned long long&>(a)),
          "l"(reinterpret_cast<unsigned long long&>(b)),
          "l"(reinterpret_cast<unsigned long long&>(c)));
    return d;
}
__device__ __forceinline__ float2 mul2(float2 a, float2 b) {
    float2 d;
    asm("mul.rn.f32x2 %0, %1, %2;"
        : "=l"(reinterpret_cast<unsigned long long&>(d))
        : "l"(reinterpret_cast<unsigned long long&>(a)),
          "l"(reinterpret_cast<unsigned long long&>(b)));
    return d;
}

__device__ __forceinline__ void cp16(uint32_t smem_dst, const void* gmem_src) {
    asm volatile("cp.async.cg.shared.global [%0], [%1], 16;"
                 :: "r"(smem_dst), "l"(gmem_src));
}

// Block = one (b,h, v-half). 256 threads: ks = tid&15 (K split 16x4),
// vg = tid>>4 (32 v's split 16x2). Each thread: 4k x 2v state tile (4 float2).
// Per step: o_v = sum_k q_k*S_kv + v_v*(sum_k q_k*u_k*k_k);  S = S*exp(w) + k*v.
// 16-lane reduction: xor8 (value-distribute 2 v's) + xor4 in-step; xor2+xor1
// deferred to the next step (pipelined).
__global__ __launch_bounds__(NTHREADS, 2)
void rwkv6_scan_kernel(const float* __restrict__ r,
                       const float* __restrict__ kin,
                       const float* __restrict__ vin,
                       const float* __restrict__ win,
                       const float* __restrict__ uin,
                       const float* __restrict__ h0,
                       float* __restrict__ o,
                       float* __restrict__ hT) {
    const int blk   = blockIdx.x;        // 0..255
    const int bh    = blk >> 1;
    const int vh    = blk & 1;           // which V half
    const int h     = bh % Hdim;
    const int tid   = threadIdx.x;
    const int ks    = tid & 15;
    const int vg    = tid >> 4;          // 0..15
    const int kbase = ks * 4;
    const int vbase = vg * 2;            // within half: 0..30
    const bool b3   = (ks & 8) != 0;
    const int vidx  = vbase + (b3 ? 1 : 0);     // v written by this lane
    const bool store_lane = (ks & 7) == 0;      // ks==0 (v0) and ks==8 (v1)

    __shared__ float sq[2][CHUNK][Kdim];   // 16 KB
    __shared__ float sk[2][CHUNK][Kdim];   // 16 KB
    __shared__ float sw[2][CHUNK][Kdim];   // 16 KB (exp applied in place)
    __shared__ float sv[2][CHUNK][VH];     //  8 KB
    __shared__ float squk[2][CHUNK];       // per-step  sum_k q*u*k
    __shared__ float su[Kdim];

    // state tile: s[v*2+p] holds S[kbase+2p .. kbase+2p+1][vglobal]
    float2 s[4];
    {
        const size_t hb = (size_t)bh * Kdim * Vdim + vh * VH + vbase;
#pragma unroll
        for (int v = 0; v < 2; v++)
#pragma unroll
            for (int p = 0; p < 2; p++) {
                s[v * 2 + p].x = h0[hb + (size_t)(kbase + 2 * p)     * Vdim + v];
                s[v * 2 + p].y = h0[hb + (size_t)(kbase + 2 * p + 1) * Vdim + v];
            }
    }
    if (tid < Kdim) su[tid] = uin[h * Kdim + tid];

    const size_t kbase_g = (size_t)bh * Tdim * Kdim;     // q/k/w base
    const size_t vbase_g = (size_t)bh * Tdim * Vdim + vh * VH;

    const uint32_t sq_s = (uint32_t)__cvta_generic_to_shared(&sq[0][0][0]);
    const uint32_t sk_s = (uint32_t)__cvta_generic_to_shared(&sk[0][0][0]);
    const uint32_t sw_s = (uint32_t)__cvta_generic_to_shared(&sw[0][0][0]);
    const uint32_t sv_s = (uint32_t)__cvta_generic_to_shared(&sv[0][0][0]);

    // issue a chunk's tensors as one cp.async group into buffer `buf`
    auto issue_chunk = [&](int c, int buf) {
        const size_t off = kbase_g + (size_t)c * CHUNK * Kdim;
#pragma unroll
        for (int half = 0; half < 2; half++) {
            const int idx = tid + half * NTHREADS;      // 0..511 (16B units)
            const uint32_t so = buf * CB_QKW + idx * 16;
            const size_t go = off + (size_t)idx * 4;
            cp16(sq_s + so, r   + go);
            cp16(sk_s + so, kin + go);
            cp16(sw_s + so, win + go);
        }
        // v half: 32 steps x 32 floats = 4 KB (one cp16 per thread)
        {
            const int stp  = tid >> 3;     // 0..31
            const int lane = tid & 7;      // 0..7
            cp16(sv_s + buf * CB_V + tid * 16,
                 vin + vbase_g + (size_t)(c * CHUNK + stp) * Vdim + lane * 4);
        }
        asm volatile("cp.async.commit_group;");
    };

    issue_chunk(0, 0);
    issue_chunk(1, 1);

    for (int c = 0; c < NCHUNK; c++) {
        const int cur = c & 1;
        asm volatile("cp.async.wait_group 1;");
        __syncthreads();

        // ---- per-chunk preprocessing ----
        // exp(w) in place: 2048 values / 256 threads = two float4 each
        {
            float4* wf = (float4*)&sw[cur][0][0];
#pragma unroll
            for (int i = 0; i < 2; i++) {
                float4 t = wf[tid + i * NTHREADS];
                t.x = __expf(t.x); t.y = __expf(t.y);
                t.z = __expf(t.z); t.w = __expf(t.w);
                wf[tid + i * NTHREADS] = t;
            }
        }
        // quk[t] = sum_k q*u*k : 32 steps x 8 lanes, 8 k's each
        {
            const int stp  = tid >> 3;           // 0..31
            const int part = tid & 7;            // 0..7
            const float4* qq = (const float4*)&sq[cur][stp][part * 8];
            const float4* kk = (const float4*)&sk[cur][stp][part * 8];
            const float4* uu = (const float4*)&su[part * 8];
            float sum = 0.f;
#pragma unroll
            for (int i = 0; i < 2; i++) {
                const float4 q4 = qq[i], k4 = kk[i], u4 = uu[i];
                sum = fmaf(q4.x * k4.x, u4.x, sum);
                sum = fmaf(q4.y * k4.y, u4.y, sum);
                sum = fmaf(q4.z * k4.z, u4.z, sum);
                sum = fmaf(q4.w * k4.w, u4.w, sum);
            }
            sum += __shfl_xor_sync(0xffffffffu, sum, 1);
            sum += __shfl_xor_sync(0xffffffffu, sum, 2);
            sum += __shfl_xor_sync(0xffffffffu, sum, 4);
            if (part == 0) squk[cur][stp] = sum;
        }
        __syncthreads();

        // ---- compute CHUNK steps, no barriers; reduction pipelined 2+2 ----
        const size_t obase = (size_t)bh * Tdim * Vdim
                           + (size_t)c * CHUNK * Vdim + vh * VH;
        float pend_red = 0.f;
        float pend_bias = 0.f;
#pragma unroll 8
        for (int tt = 0; tt < CHUNK; tt++) {
            const float4 q4 = *(const float4*)&sq[cur][tt][kbase];
            const float4 k4 = *(const float4*)&sk[cur][tt][kbase];
            const float4 e4 = *(const float4*)&sw[cur][tt][kbase];
            const float2 v2 = *(const float2*)&sv[cur][tt][vbase];

            const float2 q2a = make_float2(q4.x, q4.y);
            const float2 q2b = make_float2(q4.z, q4.w);
            const float2 k2a = make_float2(k4.x, k4.y);
            const float2 k2b = make_float2(k4.z, k4.w);
            const float2 e2a = make_float2(e4.x, e4.y);
            const float2 e2b = make_float2(e4.z, e4.w);

            float a0, a1;
            {
                const float2 vv = make_float2(v2.x, v2.x);
                const float2 kva = mul2(k2a, vv);
                const float2 kvb = mul2(k2b, vv);
                float2 acc = mul2(q2a, s[0]);
                acc = fma2(q2b, s[1], acc);
                s[0] = fma2(s[0], e2a, kva);
                s[1] = fma2(s[1], e2b, kvb);
                a0 = acc.x + acc.y;
            }
            {
                const float2 vv = make_float2(v2.y, v2.y);
                const float2 kva = mul2(k2a, vv);
                const float2 kvb = mul2(k2b, vv);
                float2 acc = mul2(q2a, s[2]);
                acc = fma2(q2b, s[3], acc);
                s[2] = fma2(s[2], e2a, kva);
                s[3] = fma2(s[3], e2b, kvb);
                a1 = acc.x + acc.y;
            }

            // finish previous step's reduction (latency long hidden)
            if (tt > 0) {
                pend_red += __shfl_xor_sync(0xffffffffu, pend_red, 2);
                pend_red += __shfl_xor_sync(0xffffffffu, pend_red, 1);
                if (store_lane)
                    o[obase + (size_t)(tt - 1) * Vdim + vidx] = pend_red + pend_bias;
            }

            // stage xor8: distribute v0 to b3=0 lanes, v1 to b3=1 lanes
            const float send = b3 ? a0 : a1;
            const float recv = __shfl_xor_sync(0xffffffffu, send, 8);
            float red = (b3 ? a1 : a0) + recv;
            // stage xor4
            red += __shfl_xor_sync(0xffffffffu, red, 4);
            pend_red = red;
            pend_bias = squk[cur][tt] * (b3 ? v2.y : v2.x);
        }
        // flush last step of the chunk
        pend_red += __shfl_xor_sync(0xffffffffu, pend_red, 2);
        pend_red += __shfl_xor_sync(0xffffffffu, pend_red, 1);
        if (store_lane)
            o[obase + (size_t)(CHUNK - 1) * Vdim + vidx] = pend_red + pend_bias;

        __syncthreads();   // all reads of `cur` done before refill

        if (c + 2 < NCHUNK)
            issue_chunk(c + 2, cur);
    }

    // final state: layout (B,H,K,V)
    {
        const size_t hb = (size_t)bh * Kdim * Vdim + vh * VH + vbase;
#pragma unroll
        for (int v = 0; v < 2; v++)
#pragma unroll
            for (int p = 0; p < 2; p++) {
                hT[hb + (size_t)(kbase + 2 * p)     * Vdim + v] = s[v * 2 + p].x;
                hT[hb + (size_t)(kbase + 2 * p + 1) * Vdim + v] = s[v * 2 + p].y;
            }
    }
}

extern "C" void kernel_launch(void* const* d_in, const int* in_sizes, int n_in,
                              void* d_out, int out_size) {
    const float* r  = (const float*)d_in[0];
    const float* k  = (const float*)d_in[1];
    const float* v  = (const float*)d_in[2];
    const float* w  = (const float*)d_in[3];
    const float* u  = (const float*)d_in[4];
    const float* h0 = (const float*)d_in[5];

    float* o  = (float*)d_out;
    float* hT = o + (size_t)Bdim * Hdim * Tdim * Vdim;

    rwkv6_scan_kernel<<<Bdim * Hdim * 2, NTHREADS>>>(r, k, v, w, u, h0, o, hT);
}

// round 14
// speedup vs baseline: 1.0017x; 1.0017x over previous
#include <cuda_runtime.h>
#include <cstdint>

#define Bdim 4
#define Hdim 32
#define Tdim 2048
#define Kdim 64
#define Vdim 64
#define VH 32                      // v-columns per block (V split in 2)
#define CHUNK 32
#define NCHUNK (Tdim / CHUNK)
#define NTHREADS 256
#define CB_QKW (CHUNK * Kdim * 4)  // 8192 B per chunk for q/k/w
#define CB_V   (CHUNK * VH * 4)    // 4096 B per chunk for v-half

// ---- packed f32x2 helpers (sm_103a FFMA2 path) ----
__device__ __forceinline__ float2 fma2(float2 a, float2 b, float2 c) {
    float2 d;
    asm("fma.rn.f32x2 %0, %1, %2, %3;"
        : "=l"(reinterpret_cast<unsigned long long&>(d))
        : "l"(reinterpret_cast<unsigned long long&>(a)),
          "l"(reinterpret_cast<unsigned long long&>(b)),
          "l"(reinterpret_cast<unsigned long long&>(c)));
    return d;
}
__device__ __forceinline__ float2 mul2(float2 a, float2 b) {
    float2 d;
    asm("mul.rn.f32x2 %0, %1, %2;"
        : "=l"(reinterpret_cast<unsigned long long&>(d))
        : "l"(reinterpret_cast<unsigned long long&>(a)),
          "l"(reinterpret_cast<unsigned long long&>(b)));
    return d;
}

__device__ __forceinline__ void cp16(uint32_t smem_dst, const void* gmem_src) {
    asm volatile("cp.async.cg.shared.global [%0], [%1], 16;"
                 :: "r"(smem_dst), "l"(gmem_src));
}

// Block = one (b,h, v-half). 256 threads: ks = tid&15 (K split 16x4),
// vg = tid>>4 (32 v's split 16x2). Each thread: 4k x 2v state tile (4 float2).
// Per step: o_v = sum_k q_k*S_kv + v_v*(sum_k q_k*u_k*k_k);  S = S*exp(w) + k*v.
// 16-lane reduction: xor8 (value-distribute 2 v's) + xor4 in-step; xor2+xor1
// deferred to the next step (pipelined).
__global__ __launch_bounds__(NTHREADS, 2)
void rwkv6_scan_kernel(const float* __restrict__ r,
                       const float* __restrict__ kin,
                       const float* __restrict__ vin,
                       const float* __restrict__ win,
                       const float* __restrict__ uin,
                       const float* __restrict__ h0,
                       float* __restrict__ o,
                       float* __restrict__ hT) {
    const int blk   = blockIdx.x;        // 0..255
    const int bh    = blk >> 1;
    const int vh    = blk & 1;           // which V half
    const int h     = bh % Hdim;
    const int tid   = threadIdx.x;
    const int ks    = tid & 15;
    const int vg    = tid >> 4;          // 0..15
    const int kbase = ks * 4;
    const int vbase = vg * 2;            // within half: 0..30
    const bool b3   = (ks & 8) != 0;
    const int vidx  = vbase + (b3 ? 1 : 0);     // v written by this lane
    const bool store_lane = (ks & 7) == 0;      // ks==0 (v0) and ks==8 (v1)

    __shared__ float sq[2][CHUNK][Kdim];   // 16 KB
    __shared__ float sk[2][CHUNK][Kdim];   // 16 KB
    __shared__ float sw[2][CHUNK][Kdim];   // 16 KB (exp applied in place)
    __shared__ float sv[2][CHUNK][VH];     //  8 KB
    __shared__ float squk[2][CHUNK];       // per-step  sum_k q*u*k
    __shared__ float su[Kdim];

    // state tile: s[v*2+p] holds S[kbase+2p .. kbase+2p+1][vglobal]
    float2 s[4];
    {
        const size_t hb = (size_t)bh * Kdim * Vdim + vh * VH + vbase;
#pragma unroll
        for (int v = 0; v < 2; v++)
#pragma unroll
            for (int p = 0; p < 2; p++) {
                s[v * 2 + p].x = h0[hb + (size_t)(kbase + 2 * p)     * Vdim + v];
                s[v * 2 + p].y = h0[hb + (size_t)(kbase + 2 * p + 1) * Vdim + v];
            }
    }
    if (tid < Kdim) su[tid] = uin[h * Kdim + tid];

    const size_t kbase_g = (size_t)bh * Tdim * Kdim;     // q/k/w base
    const size_t vbase_g = (size_t)bh * Tdim * Vdim + vh * VH;

    const uint32_t sq_s = (uint32_t)__cvta_generic_to_shared(&sq[0][0][0]);
    const uint32_t sk_s = (uint32_t)__cvta_generic_to_shared(&sk[0][0][0]);
    const uint32_t sw_s = (uint32_t)__cvta_generic_to_shared(&sw[0][0][0]);
    const uint32_t sv_s = (uint32_t)__cvta_generic_to_shared(&sv[0][0][0]);

    // issue a chunk's tensors as one cp.async group into buffer `buf`
    auto issue_chunk = [&](int c, int buf) {
        const size_t off = kbase_g + (size_t)c * CHUNK * Kdim;
#pragma unroll
        for (int half = 0; half < 2; half++) {
            const int idx = tid + half * NTHREADS;      // 0..511 (16B units)
            const uint32_t so = buf * CB_QKW + idx * 16;
            const size_t go = off + (size_t)idx * 4;
            cp16(sq_s + so, r   + go);
            cp16(sk_s + so, kin + go);
            cp16(sw_s + so, win + go);
        }
        // v half: 32 steps x 32 floats = 4 KB (one cp16 per thread)
        {
            const int stp  = tid >> 3;     // 0..31
            const int lane = tid & 7;      // 0..7
            cp16(sv_s + buf * CB_V + tid * 16,
                 vin + vbase_g + (size_t)(c * CHUNK + stp) * Vdim + lane * 4);
        }
        asm volatile("cp.async.commit_group;");
    };

    issue_chunk(0, 0);
    issue_chunk(1, 1);

    for (int c = 0; c < NCHUNK; c++) {
        const int cur = c & 1;
        asm volatile("cp.async.wait_group 1;");
        __syncthreads();

        // ---- per-chunk preprocessing ----
        // exp(w) in place: 2048 values / 256 threads = two float4 each
        {
            float4* wf = (float4*)&sw[cur][0][0];
#pragma unroll
            for (int i = 0; i < 2; i++) {
                float4 t = wf[tid + i * NTHREADS];
                t.x = __expf(t.x); t.y = __expf(t.y);
                t.z = __expf(t.z); t.w = __expf(t.w);
                wf[tid + i * NTHREADS] = t;
            }
        }
        // quk[t] = sum_k q*u*k : 32 steps x 8 lanes, 8 k's each
        {
            const int stp  = tid >> 3;           // 0..31
            const int part = tid & 7;            // 0..7
            const float4* qq = (const float4*)&sq[cur][stp][part * 8];
            const float4* kk = (const float4*)&sk[cur][stp][part * 8];
            const float4* uu = (const float4*)&su[part * 8];
            float sum = 0.f;
#pragma unroll
            for (int i = 0; i < 2; i++) {
                const float4 q4 = qq[i], k4 = kk[i], u4 = uu[i];
                sum = fmaf(q4.x * k4.x, u4.x, sum);
                sum = fmaf(q4.y * k4.y, u4.y, sum);
                sum = fmaf(q4.z * k4.z, u4.z, sum);
                sum = fmaf(q4.w * k4.w, u4.w, sum);
            }
            sum += __shfl_xor_sync(0xffffffffu, sum, 1);
            sum += __shfl_xor_sync(0xffffffffu, sum, 2);
            sum += __shfl_xor_sync(0xffffffffu, sum, 4);
            if (part == 0) squk[cur][stp] = sum;
        }
        __syncthreads();

        // ---- compute CHUNK steps, no barriers; reduction pipelined 2+2 ----
        const size_t obase = (size_t)bh * Tdim * Vdim
                           + (size_t)c * CHUNK * Vdim + vh * VH;
        float pend_red = 0.f;
        float pend_bias = 0.f;
#pragma unroll 8
        for (int tt = 0; tt < CHUNK; tt++) {
            const float4 q4 = *(const float4*)&sq[cur][tt][kbase];
            const float4 k4 = *(const float4*)&sk[cur][tt][kbase];
            const float4 e4 = *(const float4*)&sw[cur][tt][kbase];
            const float2 v2 = *(const float2*)&sv[cur][tt][vbase];

            const float2 q2a = make_float2(q4.x, q4.y);
            const float2 q2b = make_float2(q4.z, q4.w);
            const float2 k2a = make_float2(k4.x, k4.y);
            const float2 k2b = make_float2(k4.z, k4.w);
            const float2 e2a = make_float2(e4.x, e4.y);
            const float2 e2b = make_float2(e4.z, e4.w);

            float a0, a1;
            {
                const float2 vv = make_float2(v2.x, v2.x);
                const float2 kva = mul2(k2a, vv);
                const float2 kvb = mul2(k2b, vv);
                float2 acc = mul2(q2a, s[0]);
                acc = fma2(q2b, s[1], acc);
                s[0] = fma2(s[0], e2a, kva);
                s[1] = fma2(s[1], e2b, kvb);
                a0 = acc.x + acc.y;
            }
            {
                const float2 vv = make_float2(v2.y, v2.y);
                const float2 kva = mul2(k2a, vv);
                const float2 kvb = mul2(k2b, vv);
                float2 acc = mul2(q2a, s[2]);
                acc = fma2(q2b, s[3], acc);
                s[2] = fma2(s[2], e2a, kva);
                s[3] = fma2(s[3], e2b, kvb);
                a1 = acc.x + acc.y;
            }

            // finish previous step's reduction (latency long hidden)
            if (tt > 0) {
                pend_red += __shfl_xor_sync(0xffffffffu, pend_red, 2);
                pend_red += __shfl_xor_sync(0xffffffffu, pend_red, 1);
                if (store_lane)
                    o[obase + (size_t)(tt - 1) * Vdim + vidx] = pend_red + pend_bias;
            }

            // stage xor8: distribute v0 to b3=0 lanes, v1 to b3=1 lanes
            const float send = b3 ? a0 : a1;
            const float recv = __shfl_xor_sync(0xffffffffu, send, 8);
            float red = (b3 ? a1 : a0) + recv;
            // stage xor4
            red += __shfl_xor_sync(0xffffffffu, red, 4);
            pend_red = red;
            pend_bias = squk[cur][tt] * (b3 ? v2.y : v2.x);
        }
        // flush last step of the chunk
        pend_red += __shfl_xor_sync(0xffffffffu, pend_red, 2);
        pend_red += __shfl_xor_sync(0xffffffffu, pend_red, 1);
        if (store_lane)
            o[obase + (size_t)(CHUNK - 1) * Vdim + vidx] = pend_red + pend_bias;

        __syncthreads();   // all reads of `cur` done before refill

        if (c + 2 < NCHUNK)
            issue_chunk(c + 2, cur);
    }

    // final state: layout (B,H,K,V)
    {
        const size_t hb = (size_t)bh * Kdim * Vdim + vh * VH + vbase;
#pragma unroll
        for (int v = 0; v < 2; v++)
#pragma unroll
            for (int p = 0; p < 2; p++) {
                hT[hb + (size_t)(kbase + 2 * p)     * Vdim + v] = s[v * 2 + p].x;
                hT[hb + (size_t)(kbase + 2 * p + 1) * Vdim + v] = s[v * 2 + p].y;
            }
    }
}

extern "C" void kernel_launch(void* const* d_in, const int* in_sizes, int n_in,
                              void* d_out, int out_size) {
    const float* r  = (const float*)d_in[0];
    const float* k  = (const float*)d_in[1];
    const float* v  = (const float*)d_in[2];
    const float* w  = (const float*)d_in[3];
    const float* u  = (const float*)d_in[4];
    const float* h0 = (const float*)d_in[5];

    float* o  = (float*)d_out;
    float* hT = o + (size_t)Bdim * Hdim * Tdim * Vdim;

    rwkv6_scan_kernel<<<Bdim * Hdim * 2, NTHREADS>>>(r, k, v, w, u, h0, o, hT);
}

// round 15
// speedup vs baseline: 1.5740x; 1.5712x over previous
#include <cuda_runtime.h>
#include <cstdint>

#define Bdim 4
#define Hdim 32
#define Tdim 2048
#define Kdim 64
#define Vdim 64
#define CHUNK 32
#define NCHUNK (Tdim / CHUNK)
#define NTHREADS 256
#define CHUNK_BYTES (CHUNK * Kdim * 4)   // 8192 B per tensor per chunk

// ---- packed f32x2 helpers (sm_103a FFMA2 path) ----
__device__ __forceinline__ float2 fma2(float2 a, float2 b, float2 c) {
    float2 d;
    asm("fma.rn.f32x2 %0, %1, %2, %3;"
        : "=l"(reinterpret_cast<unsigned long long&>(d))
        : "l"(reinterpret_cast<unsigned long long&>(a)),
          "l"(reinterpret_cast<unsigned long long&>(b)),
          "l"(reinterpret_cast<unsigned long long&>(c)));
    return d;
}
__device__ __forceinline__ float2 mul2(float2 a, float2 b) {
    float2 d;
    asm("mul.rn.f32x2 %0, %1, %2;"
        : "=l"(reinterpret_cast<unsigned long long&>(d))
        : "l"(reinterpret_cast<unsigned long long&>(a)),
          "l"(reinterpret_cast<unsigned long long&>(b)));
    return d;
}

__device__ __forceinline__ void cp16(uint32_t smem_dst, const void* gmem_src) {
    asm volatile("cp.async.cg.shared.global [%0], [%1], 16;"
                 :: "r"(smem_dst), "l"(gmem_src));
}

// Block = one (b,h). 256 threads: ks = tid&15 (K split 16x4), vg = tid>>4 (V split 16x4).
// Each thread owns a 4k x 4v state tile in registers (8 packed float2).
// Per step: o_v = sum_k q_k*S_kv + v_v*(sum_k q_k*u_k*k_k);  S = S*exp(w) + k*v.
// Per step only xor8+xor4 run; the xor2/xor1 stages + store are batched over
// 4 steps via a value-distribution butterfly (3 SHFLs per 4 steps, all lanes
// end owning a distinct (t, v) output and store it).
__global__ __launch_bounds__(NTHREADS, 1)
void rwkv6_scan_kernel(const float* __restrict__ r,
                       const float* __restrict__ kin,
                       const float* __restrict__ vin,
                       const float* __restrict__ win,
                       const float* __restrict__ uin,
                       const float* __restrict__ h0,
                       float* __restrict__ o,
                       float* __restrict__ hT) {
    const int bh    = blockIdx.x;
    const int h     = bh % Hdim;
    const int tid   = threadIdx.x;
    const int ks    = tid & 15;
    const int vg    = tid >> 4;
    const int kbase = ks * 4;
    const int vbase = vg * 4;
    const bool b3   = (ks & 8) != 0;
    const bool b2   = (ks & 4) != 0;
    const bool c1   = (ks & 2) != 0;
    const bool c0   = (ks & 1) != 0;
    const int vidx  = vbase + (b3 ? 2 : 0) + (b2 ? 1 : 0);  // v owned by this lane

    __shared__ float sq[2][CHUNK][Kdim];
    __shared__ float sk[2][CHUNK][Kdim];
    __shared__ float sw[2][CHUNK][Kdim];   // exp() applied in place per chunk
    __shared__ float sv[2][CHUNK][Vdim];
    __shared__ float squk[2][CHUNK];       // per-step  sum_k q*u*k
    __shared__ float su[Kdim];

    // state tile: s[v*2+p] holds S[kbase+2p .. kbase+2p+1][vbase+v]
    float2 s[8];
    {
        const size_t hb = (size_t)bh * Kdim * Vdim;
#pragma unroll
        for (int v = 0; v < 4; v++)
#pragma unroll
            for (int p = 0; p < 2; p++) {
                s[v * 2 + p].x = h0[hb + (size_t)(kbase + 2 * p)     * Vdim + vbase + v];
                s[v * 2 + p].y = h0[hb + (size_t)(kbase + 2 * p + 1) * Vdim + vbase + v];
            }
    }
    if (tid < Kdim) su[tid] = uin[h * Kdim + tid];

    const size_t base = (size_t)bh * Tdim * Kdim;   // also valid for v and o (K==V)

    const uint32_t sq_s = (uint32_t)__cvta_generic_to_shared(&sq[0][0][0]);
    const uint32_t sk_s = (uint32_t)__cvta_generic_to_shared(&sk[0][0][0]);
    const uint32_t sw_s = (uint32_t)__cvta_generic_to_shared(&sw[0][0][0]);
    const uint32_t sv_s = (uint32_t)__cvta_generic_to_shared(&sv[0][0][0]);

    // issue a chunk's 4 tensors as one cp.async group into buffer `buf`
    // 8192 B per tensor = 256 threads x 2 cp16
    auto issue_chunk = [&](int c, int buf) {
        const size_t off = base + (size_t)c * CHUNK * Kdim;
        const uint32_t bofs = buf * CHUNK_BYTES + tid * 16;
#pragma unroll
        for (int half = 0; half < 2; half++) {
            const uint32_t so = bofs + half * 4096;
            const size_t go = off + half * 1024 + tid * 4;
            cp16(sq_s + so, r   + go);
            cp16(sk_s + so, kin + go);
            cp16(sw_s + so, win + go);
            cp16(sv_s + so, vin + go);
        }
        asm volatile("cp.async.commit_group;");
    };

    issue_chunk(0, 0);
    issue_chunk(1, 1);

    for (int c = 0; c < NCHUNK; c++) {
        const int cur = c & 1;
        asm volatile("cp.async.wait_group 1;");
        __syncthreads();

        // ---- per-chunk preprocessing ----
        // exp(w) in place: 2048 values / 256 threads = two float4 each
        {
            float4* wf = (float4*)&sw[cur][0][0];
#pragma unroll
            for (int i = 0; i < 2; i++) {
                float4 t = wf[tid + i * NTHREADS];
                t.x = __expf(t.x); t.y = __expf(t.y);
                t.z = __expf(t.z); t.w = __expf(t.w);
                wf[tid + i * NTHREADS] = t;
            }
        }
        // quk[t] = sum_k q*u*k : 32 steps x 8 lanes, 8 k's each
        {
            const int stp  = tid >> 3;           // 0..31
            const int part = tid & 7;            // 0..7
            const float4* qq = (const float4*)&sq[cur][stp][part * 8];
            const float4* kk = (const float4*)&sk[cur][stp][part * 8];
            const float4* uu = (const float4*)&su[part * 8];
            float sum = 0.f;
#pragma unroll
            for (int i = 0; i < 2; i++) {
                const float4 q4 = qq[i], k4 = kk[i], u4 = uu[i];
                sum = fmaf(q4.x * k4.x, u4.x, sum);
                sum = fmaf(q4.y * k4.y, u4.y, sum);
                sum = fmaf(q4.z * k4.z, u4.z, sum);
                sum = fmaf(q4.w * k4.w, u4.w, sum);
            }
            sum += __shfl_xor_sync(0xffffffffu, sum, 1);
            sum += __shfl_xor_sync(0xffffffffu, sum, 2);
            sum += __shfl_xor_sync(0xffffffffu, sum, 4);
            if (part == 0) squk[cur][stp] = sum;
        }
        __syncthreads();

        // ---- compute CHUNK steps in batches of 4, no barriers ----
        const size_t obase = base + (size_t)c * CHUNK * Vdim;
#pragma unroll 2
        for (int tb = 0; tb < CHUNK; tb += 4) {
            float P[4];   // per-step partials after xor8+xor4 (indexed compile-time)
#pragma unroll
            for (int t4 = 0; t4 < 4; t4++) {
                const int tt = tb + t4;
                const float4 q4 = *(const float4*)&sq[cur][tt][kbase];
                const float4 k4 = *(const float4*)&sk[cur][tt][kbase];
                const float4 e4 = *(const float4*)&sw[cur][tt][kbase];
                const float4 v4 = *(const float4*)&sv[cur][tt][vbase];

                const float2 q2a = make_float2(q4.x, q4.y);
                const float2 q2b = make_float2(q4.z, q4.w);
                const float2 k2a = make_float2(k4.x, k4.y);
                const float2 k2b = make_float2(k4.z, k4.w);
                const float2 e2a = make_float2(e4.x, e4.y);
                const float2 e2b = make_float2(e4.z, e4.w);
                const float vs[4] = {v4.x, v4.y, v4.z, v4.w};

                float a[4];
#pragma unroll
                for (int v = 0; v < 4; v++) {
                    const float2 vv = make_float2(vs[v], vs[v]);
                    const float2 kva = mul2(k2a, vv);
                    const float2 kvb = mul2(k2b, vv);
                    float2 acc = mul2(q2a, s[v * 2 + 0]);
                    acc = fma2(q2b, s[v * 2 + 1], acc);
                    s[v * 2 + 0] = fma2(s[v * 2 + 0], e2a, kva);
                    s[v * 2 + 1] = fma2(s[v * 2 + 1], e2b, kvb);
                    a[v] = acc.x + acc.y;
                }

                // stage xor8: distribute this lane's 4 v-partials to b3 halves
                const float sx = b3 ? a[0] : a[2];
                const float sy = b3 ? a[1] : a[3];
                const float rx = __shfl_xor_sync(0xffffffffu, sx, 8);
                const float ry = __shfl_xor_sync(0xffffffffu, sy, 8);
                const float p0 = (b3 ? a[2] : a[0]) + rx;
                const float p1 = (b3 ? a[3] : a[1]) + ry;
                // stage xor4: distribute p0/p1 over b2
                const float snd = b2 ? p0 : p1;
                const float rz = __shfl_xor_sync(0xffffffffu, snd, 4);
                P[t4] = (b2 ? p1 : p0) + rz;
            }

            // batched tail: sum over the 4 c-lanes while distributing the 4
            // steps, so lane c ends with the full o for (t = tb + c, vidx).
            // stage xor2 (2 sends)
            const float s0 = c1 ? P[0] : P[2];
            const float s1 = c1 ? P[1] : P[3];
            const float q0 = (c1 ? P[2] : P[0]) + __shfl_xor_sync(0xffffffffu, s0, 2);
            const float q1 = (c1 ? P[3] : P[1]) + __shfl_xor_sync(0xffffffffu, s1, 2);
            // stage xor1 (1 send)
            const float snd2 = c0 ? q0 : q1;
            const float red = (c0 ? q1 : q0) + __shfl_xor_sync(0xffffffffu, snd2, 1);

            const int tsel = tb + (ks & 3);
            o[obase + (size_t)tsel * Vdim + vidx] =
                fmaf(squk[cur][tsel], sv[cur][tsel][vidx], red);
        }

        __syncthreads();   // all reads of `cur` done before refill

        if (c + 2 < NCHUNK)
            issue_chunk(c + 2, cur);
    }

    // final state: layout (B,H,K,V)
    {
        const size_t hb = (size_t)bh * Kdim * Vdim;
#pragma unroll
        for (int v = 0; v < 4; v++)
#pragma unroll
            for (int p = 0; p < 2; p++) {
                hT[hb + (size_t)(kbase + 2 * p)     * Vdim + vbase + v] = s[v * 2 + p].x;
                hT[hb + (size_t)(kbase + 2 * p + 1) * Vdim + vbase + v] = s[v * 2 + p].y;
            }
    }
}

extern "C" void kernel_launch(void* const* d_in, const int* in_sizes, int n_in,
                              void* d_out, int out_size) {
    const float* r  = (const float*)d_in[0];
    const float* k  = (const float*)d_in[1];
    const float* v  = (const float*)d_in[2];
    const float* w  = (const float*)d_in[3];
    const float* u  = (const float*)d_in[4];
    const float* h0 = (const float*)d_in[5];

    float* o  = (float*)d_out;
    float* hT = o + (size_t)Bdim * Hdim * Tdim * Vdim;

    rwkv6_scan_kernel<<<Bdim * Hdim, NTHREADS>>>(r, k, v, w, u, h0, o, hT);
}